// round 12
// baseline (speedup 1.0000x reference)
#include <cuda_runtime.h>
#include <cuda_fp16.h>
#include <stdint.h>
#include <math.h>

#define NE 8
#define HID 2048
#define INTER 1408
#define TOT 8192
#define MAXTILES 96
#define MAXGRIDY 72

// ---------------------------------------------------------------------------
// Device globals (fp16 single plane everywhere)
// ---------------------------------------------------------------------------
__device__ int g_tile_expert[MAXTILES];
__device__ int g_tile_row0[MAXTILES];
__device__ int g_tile_nrows[MAXTILES];
__device__ int g_ntiles;

__device__ __half g_x[(size_t)TOT * HID];
// transposed weights: [E][N][K], K contiguous
__device__ __half g_wg[(size_t)NE * INTER * HID];
__device__ __half g_wu[(size_t)NE * INTER * HID];
__device__ __half g_wd[(size_t)NE * HID * INTER];
__device__ __half g_h[(size_t)TOT * INTER];

// ---------------------------------------------------------------------------
// Helpers (base-target PTX: mma.sync sm_80, cp.async sm_80, ldmatrix sm_75)
// ---------------------------------------------------------------------------
__device__ __forceinline__ uint32_t smem_u32(const void* p) {
    uint32_t a;
    asm("{ .reg .u64 t; cvta.to.shared.u64 t, %1; cvt.u32.u64 %0, t; }"
        : "=r"(a) : "l"(p));
    return a;
}

__device__ __forceinline__ void cp16(uint32_t dst, const void* src, int srcsize) {
    asm volatile("cp.async.cg.shared.global [%0], [%1], 16, %2;"
                 :: "r"(dst), "l"(src), "r"(srcsize));
}
#define CP_COMMIT() asm volatile("cp.async.commit_group;")
#define CP_WAIT0()  asm volatile("cp.async.wait_group 0;")

__device__ __forceinline__ void mma16816(float& c0, float& c1, float& c2, float& c3,
                                         const uint32_t a[4], const uint32_t* b) {
    asm volatile(
        "mma.sync.aligned.m16n8k16.row.col.f32.f16.f16.f32 "
        "{%0,%1,%2,%3},{%4,%5,%6,%7},{%8,%9},{%0,%1,%2,%3};"
        : "+f"(c0), "+f"(c1), "+f"(c2), "+f"(c3)
        : "r"(a[0]), "r"(a[1]), "r"(a[2]), "r"(a[3]), "r"(b[0]), "r"(b[1]));
}
#define MMA(C, A, B) mma16816((C)[0], (C)[1], (C)[2], (C)[3], A, B)

__device__ __forceinline__ void ldm_x4(uint32_t r[4], uint32_t addr) {
    asm volatile("ldmatrix.sync.aligned.m8n8.x4.shared.b16 {%0,%1,%2,%3}, [%4];"
                 : "=r"(r[0]), "=r"(r[1]), "=r"(r[2]), "=r"(r[3]) : "r"(addr));
}

// Row stride 80 B (conflict-free for cp.async stores and ldmatrix reads)
#define RSTR 80

// A fragment group (16 rows x 16 k): one ldmatrix.x4 -> mma operand order
__device__ __forceinline__ void fragA(uint32_t a[4], uint32_t tile, int rb, int k0, int lane) {
    uint32_t addr = tile + (uint32_t)(rb + (lane & 15)) * RSTR
                         + (uint32_t)(k0 + (lane >> 4) * 8) * 2;
    ldm_x4(a, addr);
}
// B fragment pair (two adjacent n-octets x 16 k from [n][k] tile)
__device__ __forceinline__ void fragB2(uint32_t b[4], uint32_t tile, int nb, int k0, int lane) {
    uint32_t addr = tile + (uint32_t)(nb + ((lane >> 4) * 8) + (lane & 7)) * RSTR
                         + (uint32_t)(k0 + ((lane >> 3) & 1) * 8) * 2;
    ldm_x4(b, addr);
}

// loaders for 128-thread CTAs: each pass covers 32 rows x 32 k-cols
__device__ __forceinline__ void load_a128(uint32_t sdst, const __half* src,
                                          int ldk, int k0, const int sz[4], int tid) {
    const int r = tid >> 2, c = tid & 3;
#pragma unroll
    for (int i = 0; i < 4; i++)
        cp16(sdst + (r + i * 32) * RSTR + c * 16,
             src + (size_t)(r + i * 32) * ldk + k0 + c * 8, sz[i]);
}
__device__ __forceinline__ void load_w64(uint32_t sdst, const __half* src,
                                         int ldk, int k0, int tid) {
    const int r = tid >> 2, c = tid & 3;
#pragma unroll
    for (int i = 0; i < 2; i++)
        cp16(sdst + (r + i * 32) * RSTR + c * 16,
             src + (size_t)(r + i * 32) * ldk + k0 + c * 8, 16);
}
__device__ __forceinline__ void load_w128(uint32_t sdst, const __half* src,
                                          int ldk, int k0, int tid) {
    const int r = tid >> 2, c = tid & 3;
#pragma unroll
    for (int i = 0; i < 4; i++)
        cp16(sdst + (r + i * 32) * RSTR + c * 16,
             src + (size_t)(r + i * 32) * ldk + k0 + c * 8, 16);
}

// ---------------------------------------------------------------------------
// Prep kernels
// ---------------------------------------------------------------------------
__global__ void convert_x(const float* __restrict__ x, const int* __restrict__ tpe) {
    if (blockIdx.x == 0 && threadIdx.x == 0) {
        int off = 0, nt = 0;
        for (int e = 0; e < NE; e++) {
            int n = tpe[e];
            for (int r = 0; r < n; r += 128) {
                g_tile_expert[nt] = e;
                g_tile_row0[nt]   = off + r;
                g_tile_nrows[nt]  = (n - r < 128) ? (n - r) : 128;
                nt++;
            }
            off += n;
        }
        g_ntiles = nt;
    }
    const size_t n4 = (size_t)TOT * HID / 4;
    for (size_t i = blockIdx.x * blockDim.x + threadIdx.x; i < n4;
         i += (size_t)gridDim.x * blockDim.x) {
        float4 v = ((const float4*)x)[i];
        __half2 p0 = __floats2half2_rn(v.x, v.y);
        __half2 p1 = __floats2half2_rn(v.z, v.w);
        ((uint2*)g_x)[i] = make_uint2(*(uint32_t*)&p0, *(uint32_t*)&p1);
    }
}

// z<NE: wg, z>=NE: wu.  [E][HID][INTER] fp32 -> [E][INTER][HID] fp16.
__global__ void transpose_cvt_gu(const float* __restrict__ wg,
                                 const float* __restrict__ wu) {
    __shared__ float t[32][33];
    const int z = blockIdx.z;
    const int e = z & (NE - 1);
    const bool isu = z >= NE;
    const float* src = (isu ? wu : wg) + (size_t)e * HID * INTER;
    __half* dst = (isu ? g_wu : g_wg) + (size_t)e * HID * INTER;
    const int k0 = blockIdx.x * 32, n0 = blockIdx.y * 32;
    const int tx = threadIdx.x, ty = threadIdx.y;
#pragma unroll
    for (int jj = 0; jj < 2; jj++) {
        const int kl = ty + jj * 16;
        float2 v = *(const float2*)(src + (size_t)(k0 + kl) * INTER + n0 + 2 * tx);
        t[kl][2 * tx] = v.x;
        t[kl][2 * tx + 1] = v.y;
    }
    __syncthreads();
#pragma unroll
    for (int jj = 0; jj < 2; jj++) {
        const int nl = ty + jj * 16;
        __half2 p = __floats2half2_rn(t[2 * tx][nl], t[2 * tx + 1][nl]);
        *(uint32_t*)(dst + (size_t)(n0 + nl) * HID + k0 + 2 * tx) = *(uint32_t*)&p;
    }
}

// [E][INTER][HID] fp32 -> [E][HID][INTER] fp16
__global__ void transpose_cvt_d(const float* __restrict__ wd) {
    __shared__ float t[32][33];
    const int e = blockIdx.z;
    const float* src = wd + (size_t)e * INTER * HID;
    __half* dst = g_wd + (size_t)e * INTER * HID;
    const int k0 = blockIdx.x * 32, n0 = blockIdx.y * 32;
    const int tx = threadIdx.x, ty = threadIdx.y;
#pragma unroll
    for (int jj = 0; jj < 2; jj++) {
        const int kl = ty + jj * 16;
        float2 v = *(const float2*)(src + (size_t)(k0 + kl) * HID + n0 + 2 * tx);
        t[kl][2 * tx] = v.x;
        t[kl][2 * tx + 1] = v.y;
    }
    __syncthreads();
#pragma unroll
    for (int jj = 0; jj < 2; jj++) {
        const int nl = ty + jj * 16;
        __half2 p = __floats2half2_rn(t[2 * tx][nl], t[2 * tx + 1][nl]);
        *(uint32_t*)(dst + (size_t)(n0 + nl) * INTER + k0 + 2 * tx) = *(uint32_t*)&p;
    }
}

// ---------------------------------------------------------------------------
// Fused gate+up grouped GEMM (fp16). CTA: M=128 x N=64 (per matrix), BK=32.
// 4 warps (2M x 2N), warp tile 64 x 32 per matrix -> 128 B smem / MMA.
// Stage (20480 B): A 0 (10240), G 10240 (5120), U 15360 (5120)
// ---------------------------------------------------------------------------
#define GU_BUF 20480
#define GU_SMEM (2 * GU_BUF)

__global__ void __launch_bounds__(128, 2) k_gateup() {
    const int t = blockIdx.y;
    if (t >= g_ntiles) return;
    const int e     = __ldg(&g_tile_expert[t]);
    const int row0  = __ldg(&g_tile_row0[t]);
    const int nrows = __ldg(&g_tile_nrows[t]);
    const int n0    = blockIdx.x * 64;

    extern __shared__ char smem[];
    const uint32_t sb = smem_u32(smem);
    const int tid  = threadIdx.x;
    const int lane = tid & 31;
    const int wid  = tid >> 5;
    const int wm   = wid & 1;   // 2 M-halves of 64
    const int wn   = wid >> 1;  // 2 N-halves of 32 (per matrix)
    int sz[4];
#pragma unroll
    for (int i = 0; i < 4; i++) sz[i] = ((tid >> 2) + i * 32 < nrows) ? 16 : 0;

    const __half* xp = g_x + (size_t)row0 * HID;
    const size_t wbase = (size_t)e * INTER * HID + (size_t)n0 * HID;
    const __half* gp = g_wg + wbase;
    const __half* up = g_wu + wbase;

    float cg[4][4][4], cu[4][4][4];
#pragma unroll
    for (int i = 0; i < 4; i++)
#pragma unroll
        for (int j = 0; j < 4; j++)
#pragma unroll
            for (int k = 0; k < 4; k++) { cg[i][j][k] = 0.f; cu[i][j][k] = 0.f; }

#define GU_LOAD(b, k0)                                          \
    do {                                                        \
        uint32_t o = sb + (b) * GU_BUF;                         \
        load_a128(o,          xp, HID, (k0), sz, tid);          \
        load_w64(o + 10240,   gp, HID, (k0), tid);              \
        load_w64(o + 15360,   up, HID, (k0), tid);              \
        CP_COMMIT();                                            \
    } while (0)

    GU_LOAD(0, 0);
    const int KT = HID / 32;
    for (int kt = 0; kt < KT; kt++) {
        CP_WAIT0();
        __syncthreads();
        if (kt + 1 < KT) GU_LOAD((kt + 1) & 1, (kt + 1) * 32);
        const uint32_t buf = sb + (kt & 1) * GU_BUF;
#pragma unroll
        for (int ks = 0; ks < 2; ks++) {
            const int k0 = ks * 16;
            uint32_t A[4][4];
#pragma unroll
            for (int mt = 0; mt < 4; mt++)
                fragA(A[mt], buf, wm * 64 + mt * 16, k0, lane);
            uint32_t Bg[2][4], Bu[2][4];
#pragma unroll
            for (int p = 0; p < 2; p++) {
                fragB2(Bg[p], buf + 10240, wn * 32 + p * 16, k0, lane);
                fragB2(Bu[p], buf + 15360, wn * 32 + p * 16, k0, lane);
            }
#pragma unroll
            for (int p = 0; p < 2; p++)
#pragma unroll
                for (int no = 0; no < 2; no++) {
                    const int q = p * 2 + no;
#pragma unroll
                    for (int mt = 0; mt < 4; mt++) {
                        MMA(cg[mt][q], A[mt], Bg[p] + no * 2);
                        MMA(cu[mt][q], A[mt], Bu[p] + no * 2);
                    }
                }
        }
    }

    // epilogue: silu(gate)*up -> h (fp16)
#pragma unroll
    for (int mt = 0; mt < 4; mt++)
#pragma unroll
        for (int half = 0; half < 2; half++) {
            const int r = wm * 64 + mt * 16 + half * 8 + (lane >> 2);
            if (r < nrows) {
                __half* hp = g_h + (size_t)(row0 + r) * INTER + n0 + wn * 32;
#pragma unroll
                for (int q = 0; q < 4; q++) {
                    const float gg0 = cg[mt][q][half * 2], gg1 = cg[mt][q][half * 2 + 1];
                    const float uu0 = cu[mt][q][half * 2], uu1 = cu[mt][q][half * 2 + 1];
                    const float h0 = uu0 * gg0 / (1.f + __expf(-gg0));
                    const float h1 = uu1 * gg1 / (1.f + __expf(-gg1));
                    __half2 pk = __floats2half2_rn(h0, h1);
                    *(uint32_t*)(hp + q * 8 + (lane & 3) * 2) = *(uint32_t*)&pk;
                }
            }
        }
}

// ---------------------------------------------------------------------------
// Down grouped GEMM (fp16). CTA: M=128 x N=128, BK=32.
// 4 warps (2M x 2N), warp tile 64 x 64 -> 128 B smem / MMA.
// Stage (20480 B): A 0 (10240), B 10240 (10240)
// ---------------------------------------------------------------------------
#define DN_BUF 20480
#define DN_SMEM (2 * DN_BUF)

__global__ void __launch_bounds__(128, 2) k_down(const float* __restrict__ probs,
                                                 float* __restrict__ out) {
    const int t = blockIdx.y;
    if (t >= g_ntiles) return;
    const int e     = __ldg(&g_tile_expert[t]);
    const int row0  = __ldg(&g_tile_row0[t]);
    const int nrows = __ldg(&g_tile_nrows[t]);
    const int n0    = blockIdx.x * 128;

    extern __shared__ char smem[];
    const uint32_t sb = smem_u32(smem);
    const int tid  = threadIdx.x;
    const int lane = tid & 31;
    const int wid  = tid >> 5;
    const int wm   = wid & 1;
    const int wn   = wid >> 1;
    int sz[4];
#pragma unroll
    for (int i = 0; i < 4; i++) sz[i] = ((tid >> 2) + i * 32 < nrows) ? 16 : 0;

    const __half* ap = g_h + (size_t)row0 * INTER;
    const size_t wbase = (size_t)e * HID * INTER + (size_t)n0 * INTER;
    const __half* bp = g_wd + wbase;

    float cc[4][8][4];
#pragma unroll
    for (int i = 0; i < 4; i++)
#pragma unroll
        for (int j = 0; j < 8; j++)
#pragma unroll
            for (int k = 0; k < 4; k++) cc[i][j][k] = 0.f;

#define DN_LOAD(b, k0)                                          \
    do {                                                        \
        uint32_t o = sb + (b) * DN_BUF;                         \
        load_a128(o,          ap, INTER, (k0), sz, tid);        \
        load_w128(o + 10240,  bp, INTER, (k0), tid);            \
        CP_COMMIT();                                            \
    } while (0)

    DN_LOAD(0, 0);
    const int KT = INTER / 32;
    for (int kt = 0; kt < KT; kt++) {
        CP_WAIT0();
        __syncthreads();
        if (kt + 1 < KT) DN_LOAD((kt + 1) & 1, (kt + 1) * 32);
        const uint32_t buf = sb + (kt & 1) * DN_BUF;
#pragma unroll
        for (int ks = 0; ks < 2; ks++) {
            const int k0 = ks * 16;
            uint32_t A[4][4];
#pragma unroll
            for (int mt = 0; mt < 4; mt++)
                fragA(A[mt], buf, wm * 64 + mt * 16, k0, lane);
#pragma unroll
            for (int p = 0; p < 4; p++) {
                uint32_t Fb[4];
                fragB2(Fb, buf + 10240, wn * 64 + p * 16, k0, lane);
#pragma unroll
                for (int no = 0; no < 2; no++) {
                    const int q = p * 2 + no;
#pragma unroll
                    for (int mt = 0; mt < 4; mt++)
                        MMA(cc[mt][q], A[mt], Fb + no * 2);
                }
            }
        }
    }

    // epilogue: scale by probs, write fp32 out
#pragma unroll
    for (int mt = 0; mt < 4; mt++)
#pragma unroll
        for (int half = 0; half < 2; half++) {
            const int r = wm * 64 + mt * 16 + half * 8 + (lane >> 2);
            if (r < nrows) {
                const float p = probs[row0 + r];
                float* op = out + (size_t)(row0 + r) * HID + n0 + wn * 64;
#pragma unroll
                for (int q = 0; q < 8; q++) {
                    const int col = q * 8 + (lane & 3) * 2;
                    float2 v;
                    v.x = p * cc[mt][q][half * 2];
                    v.y = p * cc[mt][q][half * 2 + 1];
                    *(float2*)(op + col) = v;
                }
            }
        }
}

// ---------------------------------------------------------------------------
// Launch
// ---------------------------------------------------------------------------
extern "C" void kernel_launch(void* const* d_in, const int* in_sizes, int n_in,
                              void* d_out, int out_size) {
    const float* x     = (const float*)d_in[0];
    const float* probs = (const float*)d_in[1];
    const float* wg    = (const float*)d_in[2];
    const float* wu    = (const float*)d_in[3];
    const float* wd    = (const float*)d_in[4];
    const int*   tpe   = (const int*)d_in[5];
    float*       out   = (float*)d_out;

    cudaFuncSetAttribute(k_gateup, cudaFuncAttributeMaxDynamicSharedMemorySize, GU_SMEM);
    cudaFuncSetAttribute(k_down,   cudaFuncAttributeMaxDynamicSharedMemorySize, DN_SMEM);

    convert_x<<<2048, 256>>>(x, tpe);

    dim3 tb(16, 16);
    transpose_cvt_gu<<<dim3(HID / 32, INTER / 32, 2 * NE), tb>>>(wg, wu);
    transpose_cvt_d<<<dim3(INTER / 32, HID / 32, NE), tb>>>(wd);

    k_gateup<<<dim3(INTER / 64, MAXGRIDY), 128, GU_SMEM>>>();
    k_down<<<dim3(HID / 128, MAXGRIDY), 128, DN_SMEM>>>(probs, out);
}